// round 15
// baseline (speedup 1.0000x reference)
#include <cuda_runtime.h>
#include <cuda_fp16.h>
#include <cstdint>
#include <cstddef>

#define N_NODES 100000
#define D 128
#define CAP 96            // fixed bucket capacity (Poisson(32): P(>=96) ~ 1e-13)

// ---- device scratch (allocation-free rule: __device__ globals) ----
__device__ __align__(16) __half g_hnh[(size_t)N_NODES * D];    // 25.6 MB
__device__ __align__(16) __half g_feath[(size_t)N_NODES * D];  // 25.6 MB
__device__ __align__(16) int g_count[N_NODES];
__device__ __align__(16) int g_csr[(size_t)N_NODES * CAP];     // 38.4 MB
// W transposed to [half][n][k] fp16 (row stride 128 halfs)
__device__ __align__(16) __half g_Wh[2][128 * 128];
__device__ __align__(16) float g_bias[D];

// ===========================================================================
// helpers
// ===========================================================================
__device__ __forceinline__ void mma_f16(float& c0, float& c1, float& c2, float& c3,
                                        uint32_t a0, uint32_t a1, uint32_t a2, uint32_t a3,
                                        uint32_t b0, uint32_t b1) {
    asm volatile(
        "mma.sync.aligned.m16n8k16.row.col.f32.f16.f16.f32 "
        "{%0,%1,%2,%3}, {%4,%5,%6,%7}, {%8,%9}, {%0,%1,%2,%3};"
        : "+f"(c0), "+f"(c1), "+f"(c2), "+f"(c3)
        : "r"(a0), "r"(a1), "r"(a2), "r"(a3), "r"(b0), "r"(b1));
}

__device__ __forceinline__ void ldsm_x4(uint32_t& r0, uint32_t& r1,
                                        uint32_t& r2, uint32_t& r3, uint32_t saddr) {
    asm volatile(
        "ldmatrix.sync.aligned.m8n8.x4.shared.b16 {%0,%1,%2,%3}, [%4];"
        : "=r"(r0), "=r"(r1), "=r"(r2), "=r"(r3) : "r"(saddr));
}

__device__ __forceinline__ uint32_t h2_bits(__half2 h) {
    __half2_raw r = *reinterpret_cast<__half2_raw*>(&h);
    return (uint32_t)r.x | ((uint32_t)r.y << 16);
}
__device__ __forceinline__ __half2 bits_h2(uint32_t u) {
    __half2_raw r;
    r.x = (unsigned short)(u & 0xFFFF);
    r.y = (unsigned short)(u >> 16);
    return *reinterpret_cast<__half2*>(&r);
}

// ===========================================================================
// prep (one launch): W transpose -> fp16 images, fused bias, zero counters,
// feat fp32 -> fp16 image. Grid-stride everything.
// ===========================================================================
__global__ void prep_kernel(const float* __restrict__ feat,
                            const float* __restrict__ Wself,
                            const float* __restrict__ Wneigh,
                            const float* __restrict__ bself,
                            const float* __restrict__ bneigh) {
    const int gsz = gridDim.x * blockDim.x;
    const int gtid = blockIdx.x * blockDim.x + threadIdx.x;

    if (gtid < 128) g_bias[gtid] = bself[gtid] + bneigh[gtid];
    for (int i = gtid; i < N_NODES; i += gsz) g_count[i] = 0;
    for (int i = gtid; i < 2 * 128 * 128; i += gsz) {
        const int h = i >> 14;
        const int n = (i >> 7) & 127;
        const int k = i & 127;
        const float* W = h ? Wneigh : Wself;
        g_Wh[h][n * 128 + k] = __float2half(W[k * 128 + n]);   // B[n][k] = W[k][n]
    }
    const size_t n4 = (size_t)N_NODES * D / 4;
    for (size_t j = gtid; j < n4; j += gsz) {
        float4 v = reinterpret_cast<const float4*>(feat)[j];
        const __half2 p0 = __floats2half2_rn(v.x, v.y);
        const __half2 p1 = __floats2half2_rn(v.z, v.w);
        reinterpret_cast<uint2*>(g_feath)[j] = make_uint2(h2_bits(p0), h2_bits(p1));
    }
}

// ===========================================================================
// edges: rank = atomicAdd(count[dst]) doubles as histogram + CSR slot index
// ===========================================================================
__global__ void edges_kernel(const int* __restrict__ src,
                             const int* __restrict__ dst, int E) {
    const int gsz = gridDim.x * blockDim.x;
    const int gtid = blockIdx.x * blockDim.x + threadIdx.x;
    const int n4 = E >> 2;
    const int4* d4 = reinterpret_cast<const int4*>(dst);
    const int4* s4 = reinterpret_cast<const int4*>(src);
    for (int i = gtid; i < n4; i += gsz) {
        const int4 d = d4[i];
        const int4 s = s4[i];
        const int r0 = atomicAdd(&g_count[d.x], 1);
        const int r1 = atomicAdd(&g_count[d.y], 1);
        const int r2 = atomicAdd(&g_count[d.z], 1);
        const int r3 = atomicAdd(&g_count[d.w], 1);
        if (r0 < CAP) g_csr[(size_t)d.x * CAP + r0] = s.x;
        if (r1 < CAP) g_csr[(size_t)d.y * CAP + r1] = s.y;
        if (r2 < CAP) g_csr[(size_t)d.z * CAP + r2] = s.z;
        if (r3 < CAP) g_csr[(size_t)d.w * CAP + r3] = s.w;
    }
    for (int e = (n4 << 2) + gtid; e < E; e += gsz) {
        const int de = dst[e];
        const int r = atomicAdd(&g_count[de], 1);
        if (r < CAP) g_csr[(size_t)de * CAP + r] = src[e];
    }
}

// ===========================================================================
// aggregate: one warp per node, fp16 gathers, fp32 accumulate, fp16 store
// ===========================================================================
__global__ __launch_bounds__(256) void agg_kernel() {
    const int lane = threadIdx.x & 31;
    const int node = (blockIdx.x * blockDim.x + threadIdx.x) >> 5;
    if (node >= N_NODES) return;

    const int cnt_raw = g_count[node];
    const int cnt = (cnt_raw < CAP) ? cnt_raw : CAP;
    const int* bucket = g_csr + (size_t)node * CAP;
    const uint2* fb = reinterpret_cast<const uint2*>(g_feath) + lane;

    float4 acc = make_float4(0.f, 0.f, 0.f, 0.f);
    int t = 0;
    for (; t + 4 <= cnt; t += 4) {
        const int s0 = bucket[t + 0];
        const int s1 = bucket[t + 1];
        const int s2 = bucket[t + 2];
        const int s3 = bucket[t + 3];
        const uint2 u0 = fb[(size_t)s0 * 32];
        const uint2 u1 = fb[(size_t)s1 * 32];
        const uint2 u2 = fb[(size_t)s2 * 32];
        const uint2 u3 = fb[(size_t)s3 * 32];
        float2 f;
        f = __half22float2(bits_h2(u0.x)); acc.x += f.x; acc.y += f.y;
        f = __half22float2(bits_h2(u0.y)); acc.z += f.x; acc.w += f.y;
        f = __half22float2(bits_h2(u1.x)); acc.x += f.x; acc.y += f.y;
        f = __half22float2(bits_h2(u1.y)); acc.z += f.x; acc.w += f.y;
        f = __half22float2(bits_h2(u2.x)); acc.x += f.x; acc.y += f.y;
        f = __half22float2(bits_h2(u2.y)); acc.z += f.x; acc.w += f.y;
        f = __half22float2(bits_h2(u3.x)); acc.x += f.x; acc.y += f.y;
        f = __half22float2(bits_h2(u3.y)); acc.z += f.x; acc.w += f.y;
    }
    for (; t < cnt; ++t) {
        const int s = bucket[t];
        const uint2 u = fb[(size_t)s * 32];
        float2 f;
        f = __half22float2(bits_h2(u.x)); acc.x += f.x; acc.y += f.y;
        f = __half22float2(bits_h2(u.y)); acc.z += f.x; acc.w += f.y;
    }
    const float r = 1.0f / fmaxf((float)cnt, 1.0f);
    const __half2 p0 = __floats2half2_rn(acc.x * r, acc.y * r);
    const __half2 p1 = __floats2half2_rn(acc.z * r, acc.w * r);
    *reinterpret_cast<uint2*>(g_hnh + (size_t)node * D + lane * 4) =
        make_uint2(h2_bits(p0), h2_bits(p1));
}

// ===========================================================================
// GEMM (persistent): out = [feat16 | hn16] (M x 256) @ Wh + bias.
// Grid = 296 persistent CTAs (2/SM). Full B (256 rows x 128 halfs) resident
// in smem; A double-buffered per 64-K chunk; fragments via ldmatrix.x4.
// smem: Bful u32[256][68] (69.6KB) + A2 u32[2][128][36] (36.9KB) = 106.5KB
// ===========================================================================
#define AROW 36   // A row stride in u32 (36%32=4 -> conflict-free ldmatrix)
#define BROW 68   // B row stride in u32 (68%32=4 -> conflict-free ldmatrix)
#define GEMM_GRID 296

__global__ __launch_bounds__(256, 2) void gemm_kernel(
    float* __restrict__ out, int M, int ntiles) {
    extern __shared__ uint32_t dyn[];
    uint32_t* Bful = dyn;                       // [256][BROW]
    uint32_t* Abuf = dyn + 256 * BROW;          // [2][128][AROW]

    const int tid  = threadIdx.x;
    const int wid  = tid >> 5;
    const int lane = tid & 31;

    const int wm = wid >> 2;               // 0..1 -> rows wm*64
    const int wn = wid & 3;                // 0..3 -> cols wn*32

    const uint32_t B_base  = (uint32_t)__cvta_generic_to_shared(Bful);
    const uint32_t A_base  = (uint32_t)__cvta_generic_to_shared(Abuf);

    // ldmatrix per-lane selectors
    const int lm_r  = (lane & 7) + ((lane >> 3) & 1) * 8;  // A row ofs
    const int lm_c  = (lane >> 4) * 4;                     // A k u32 ofs
    const int lmb_r = (lane & 7) + (lane >> 4) * 8;        // B row ofs
    const int lmb_c = ((lane >> 3) & 1) * 4;               // B k u32 ofs

    // ---- load full B once: 256 rows x 16 uint4 = 4096 uint4, 16/thread ----
    {
        const uint4* Wsrc = reinterpret_cast<const uint4*>(g_Wh);
#pragma unroll
        for (int j = 0; j < 16; ++j) {
            const int slot = j * 256 + tid;    // 0..4095
            const int row  = slot >> 4;
            const int c    = slot & 15;
            *reinterpret_cast<uint4*>(&Bful[row * BROW + c * 4]) = Wsrc[slot];
        }
    }

    // A-chunk load-slot indexing: 128 rows x 8 uint4 = 1024, 4/thread
    const int lr[4] = { (0 * 256 + tid) >> 3, (1 * 256 + tid) >> 3,
                        (2 * 256 + tid) >> 3, (3 * 256 + tid) >> 3 };
    const int lc[4] = { (0 * 256 + tid) & 7, (1 * 256 + tid) & 7,
                        (2 * 256 + tid) & 7, (3 * 256 + tid) & 7 };

    uint4 apf[4];

    auto load_a = [&](int blockRow, int it) {
        const int cbase = (it & 1) * 64;
        const __half* Ag = (it >> 1) ? g_hnh : g_feath;
#pragma unroll
        for (int j = 0; j < 4; ++j) {
            const int grow = blockRow + lr[j];
            apf[j] = (grow < M)
                ? *reinterpret_cast<const uint4*>(
                      Ag + (size_t)grow * D + cbase + lc[j] * 8)
                : make_uint4(0u, 0u, 0u, 0u);
        }
    };
    auto store_a = [&](int buf) {
        uint32_t* Ab = Abuf + buf * 128 * AROW;
#pragma unroll
        for (int j = 0; j < 4; ++j)
            *reinterpret_cast<uint4*>(&Ab[lr[j] * AROW + lc[j] * 4]) = apf[j];
    };

#pragma unroll 1
    for (int tile = blockIdx.x; tile < ntiles; tile += GEMM_GRID) {
        const int blockRow = tile * 128;

        float acc[4][4][4];
#pragma unroll
        for (int mt = 0; mt < 4; ++mt)
#pragma unroll
            for (int nt = 0; nt < 4; ++nt)
#pragma unroll
                for (int j = 0; j < 4; ++j) acc[mt][nt][j] = 0.f;

        load_a(blockRow, 0);
        store_a(0);
        __syncthreads();

#pragma unroll 1
        for (int it = 0; it < 4; ++it) {
            if (it + 1 < 4) load_a(blockRow, it + 1);

            const uint32_t Ab = A_base + (uint32_t)((it & 1) * 128 * AROW * 4);
            const int bRowBase = (it >> 1) * 128;
            const int bColBase = (it & 1) * 32;

#pragma unroll
            for (int ks = 0; ks < 4; ++ks) {
                const int kb = ks * 8;
                uint32_t a[4][4], bb[2][4];
#pragma unroll
                for (int mt = 0; mt < 4; ++mt) {
                    const int rb = wm * 64 + mt * 16;
                    const uint32_t sa = Ab + (((rb + lm_r) * AROW + kb + lm_c) << 2);
                    ldsm_x4(a[mt][0], a[mt][1], a[mt][2], a[mt][3], sa);
                }
#pragma unroll
                for (int p = 0; p < 2; ++p) {
                    const int nb = bRowBase + wn * 32 + p * 16;
                    const uint32_t sb =
                        B_base + (((nb + lmb_r) * BROW + bColBase + kb + lmb_c) << 2);
                    ldsm_x4(bb[p][0], bb[p][1], bb[p][2], bb[p][3], sb);
                }
#pragma unroll
                for (int mt = 0; mt < 4; ++mt)
#pragma unroll
                    for (int nt = 0; nt < 4; ++nt)
                        mma_f16(acc[mt][nt][0], acc[mt][nt][1],
                                acc[mt][nt][2], acc[mt][nt][3],
                                a[mt][0], a[mt][1], a[mt][2], a[mt][3],
                                bb[nt >> 1][(nt & 1) * 2],
                                bb[nt >> 1][(nt & 1) * 2 + 1]);
            }

            if (it + 1 < 4) {
                store_a((it + 1) & 1);     // other buffer: safe before sync
                __syncthreads();
            }
        }

        // ---- epilogue ----
#pragma unroll
        for (int mt = 0; mt < 4; ++mt) {
            const int r0 = blockRow + wm * 64 + mt * 16 + (lane >> 2);
#pragma unroll
            for (int nt = 0; nt < 4; ++nt) {
                const int col = wn * 32 + nt * 8 + (lane & 3) * 2;
                const float b0 = g_bias[col];
                const float b1 = g_bias[col + 1];
                if (r0 < M) {
                    float2 o = make_float2(acc[mt][nt][0] + b0, acc[mt][nt][1] + b1);
                    *reinterpret_cast<float2*>(out + (size_t)r0 * D + col) = o;
                }
                if (r0 + 8 < M) {
                    float2 o = make_float2(acc[mt][nt][2] + b0, acc[mt][nt][3] + b1);
                    *reinterpret_cast<float2*>(out + (size_t)(r0 + 8) * D + col) = o;
                }
            }
        }
        __syncthreads();   // all warps done with A buffers before next tile
    }
}

// ---------------------------------------------------------------------------
extern "C" void kernel_launch(void* const* d_in, const int* in_sizes, int n_in,
                              void* d_out, int out_size) {
    const float* feat   = (const float*)d_in[0];
    const int*   src    = (const int*)d_in[1];
    const int*   dst    = (const int*)d_in[2];
    const float* Wself  = (const float*)d_in[3];
    const float* bself  = (const float*)d_in[4];
    const float* Wneigh = (const float*)d_in[5];
    const float* bneigh = (const float*)d_in[6];
    float*       out    = (float*)d_out;

    const int E = in_sizes[1];
    const int M = in_sizes[0] / D;
    const int ntiles = (M + 127) / 128;
    const int GEMM_SMEM = (256 * BROW + 2 * 128 * AROW) * 4;   // 106496 B

    cudaFuncSetAttribute(gemm_kernel, cudaFuncAttributeMaxDynamicSharedMemorySize,
                         GEMM_SMEM);

    prep_kernel<<<1024, 256>>>(feat, Wself, Wneigh, bself, bneigh);
    edges_kernel<<<148 * 8, 256>>>(src, dst, E);
    agg_kernel<<<(N_NODES * 32 + 255) / 256, 256>>>();
    gemm_kernel<<<GEMM_GRID, 256, GEMM_SMEM>>>(out, M, ntiles);
}

// round 17
// speedup vs baseline: 1.0199x; 1.0199x over previous
#include <cuda_runtime.h>
#include <cuda_fp16.h>
#include <cstdint>
#include <cstddef>

#define N_NODES 100000
#define D 128
#define CAP 96            // fixed bucket capacity (Poisson(32): P(>=96) ~ 1e-13)

// ---- device scratch (allocation-free rule: __device__ globals) ----
__device__ __align__(16) __half g_hnh[(size_t)N_NODES * D];    // 25.6 MB
__device__ __align__(16) __half g_feath[(size_t)N_NODES * D];  // 25.6 MB
__device__ __align__(16) int g_count[N_NODES];
__device__ __align__(16) int g_csr[(size_t)N_NODES * CAP];     // 38.4 MB
// W transposed to [half][n][k] fp16 (row stride 128 halfs)
__device__ __align__(16) __half g_Wh[2][128 * 128];
__device__ __align__(16) float g_bias[D];

// ===========================================================================
// helpers
// ===========================================================================
__device__ __forceinline__ void mma_f16(float& c0, float& c1, float& c2, float& c3,
                                        uint32_t a0, uint32_t a1, uint32_t a2, uint32_t a3,
                                        uint32_t b0, uint32_t b1) {
    asm volatile(
        "mma.sync.aligned.m16n8k16.row.col.f32.f16.f16.f32 "
        "{%0,%1,%2,%3}, {%4,%5,%6,%7}, {%8,%9}, {%0,%1,%2,%3};"
        : "+f"(c0), "+f"(c1), "+f"(c2), "+f"(c3)
        : "r"(a0), "r"(a1), "r"(a2), "r"(a3), "r"(b0), "r"(b1));
}

__device__ __forceinline__ void ldsm_x4(uint32_t& r0, uint32_t& r1,
                                        uint32_t& r2, uint32_t& r3, uint32_t saddr) {
    asm volatile(
        "ldmatrix.sync.aligned.m8n8.x4.shared.b16 {%0,%1,%2,%3}, [%4];"
        : "=r"(r0), "=r"(r1), "=r"(r2), "=r"(r3) : "r"(saddr));
}

__device__ __forceinline__ uint32_t h2_bits(__half2 h) {
    __half2_raw r = *reinterpret_cast<__half2_raw*>(&h);
    return (uint32_t)r.x | ((uint32_t)r.y << 16);
}
__device__ __forceinline__ __half2 bits_h2(uint32_t u) {
    __half2_raw r;
    r.x = (unsigned short)(u & 0xFFFF);
    r.y = (unsigned short)(u >> 16);
    return *reinterpret_cast<__half2*>(&r);
}

// ===========================================================================
// prep0: W transpose -> fp16 images, fused bias, zero counters
// ===========================================================================
__global__ void prep0_kernel(const float* __restrict__ Wself,
                             const float* __restrict__ Wneigh,
                             const float* __restrict__ bself,
                             const float* __restrict__ bneigh) {
    const int gsz = gridDim.x * blockDim.x;
    const int gtid = blockIdx.x * blockDim.x + threadIdx.x;

    if (gtid < 128) g_bias[gtid] = bself[gtid] + bneigh[gtid];
    for (int i = gtid; i < N_NODES; i += gsz) g_count[i] = 0;
    for (int i = gtid; i < 2 * 128 * 128; i += gsz) {
        const int h = i >> 14;
        const int n = (i >> 7) & 127;
        const int k = i & 127;
        const float* W = h ? Wneigh : Wself;
        g_Wh[h][n * 128 + k] = __float2half(W[k * 128 + n]);   // B[n][k] = W[k][n]
    }
}

// ===========================================================================
// ec: edges + cvt in ONE kernel, parity-staggered order.
//   Every block owns a grid-stride share of BOTH workloads; even blocks run
//   edges-then-cvt, odd blocks cvt-then-edges. edges saturates the L2-atomic
//   pipe with half the grid (measured issue=1.7%), cvt saturates DRAM with
//   the other half -> the two phases overlap instead of summing.
// ===========================================================================
#define EC_BLOCKS 1536

__device__ __forceinline__ void do_edges(const int* __restrict__ src,
                                         const int* __restrict__ dst, int E,
                                         int gtid, int gsz) {
    const int n4 = E >> 2;
    const int4* d4 = reinterpret_cast<const int4*>(dst);
    const int4* s4 = reinterpret_cast<const int4*>(src);
    for (int i = gtid; i < n4; i += gsz) {
        const int4 d = d4[i];
        const int4 s = s4[i];
        const int r0 = atomicAdd(&g_count[d.x], 1);
        const int r1 = atomicAdd(&g_count[d.y], 1);
        const int r2 = atomicAdd(&g_count[d.z], 1);
        const int r3 = atomicAdd(&g_count[d.w], 1);
        if (r0 < CAP) g_csr[(size_t)d.x * CAP + r0] = s.x;
        if (r1 < CAP) g_csr[(size_t)d.y * CAP + r1] = s.y;
        if (r2 < CAP) g_csr[(size_t)d.z * CAP + r2] = s.z;
        if (r3 < CAP) g_csr[(size_t)d.w * CAP + r3] = s.w;
    }
    for (int e = (n4 << 2) + gtid; e < E; e += gsz) {
        const int de = dst[e];
        const int r = atomicAdd(&g_count[de], 1);
        if (r < CAP) g_csr[(size_t)de * CAP + r] = src[e];
    }
}

__device__ __forceinline__ void do_cvt(const float* __restrict__ feat,
                                       size_t gtid, size_t gsz) {
    const size_t n4 = (size_t)N_NODES * D / 4;
    for (size_t j = gtid; j < n4; j += gsz) {
        float4 v = reinterpret_cast<const float4*>(feat)[j];
        const __half2 p0 = __floats2half2_rn(v.x, v.y);
        const __half2 p1 = __floats2half2_rn(v.z, v.w);
        reinterpret_cast<uint2*>(g_feath)[j] = make_uint2(h2_bits(p0), h2_bits(p1));
    }
}

__global__ void ec_kernel(const float* __restrict__ feat,
                          const int* __restrict__ src,
                          const int* __restrict__ dst, int E) {
    const int gsz  = gridDim.x * blockDim.x;
    const int gtid = blockIdx.x * blockDim.x + threadIdx.x;

    if ((blockIdx.x & 1) == 0) {
        do_edges(src, dst, E, gtid, gsz);
        do_cvt(feat, (size_t)gtid, (size_t)gsz);
    } else {
        do_cvt(feat, (size_t)gtid, (size_t)gsz);
        do_edges(src, dst, E, gtid, gsz);
    }
}

// ===========================================================================
// aggregate: one warp per node, fp16 gathers, fp32 accumulate, fp16 store
// ===========================================================================
__global__ __launch_bounds__(256) void agg_kernel() {
    const int lane = threadIdx.x & 31;
    const int node = (blockIdx.x * blockDim.x + threadIdx.x) >> 5;
    if (node >= N_NODES) return;

    const int cnt_raw = g_count[node];
    const int cnt = (cnt_raw < CAP) ? cnt_raw : CAP;
    const int* bucket = g_csr + (size_t)node * CAP;
    const uint2* fb = reinterpret_cast<const uint2*>(g_feath) + lane;

    float4 acc = make_float4(0.f, 0.f, 0.f, 0.f);
    int t = 0;
    for (; t + 4 <= cnt; t += 4) {
        const int s0 = bucket[t + 0];
        const int s1 = bucket[t + 1];
        const int s2 = bucket[t + 2];
        const int s3 = bucket[t + 3];
        const uint2 u0 = fb[(size_t)s0 * 32];
        const uint2 u1 = fb[(size_t)s1 * 32];
        const uint2 u2 = fb[(size_t)s2 * 32];
        const uint2 u3 = fb[(size_t)s3 * 32];
        float2 f;
        f = __half22float2(bits_h2(u0.x)); acc.x += f.x; acc.y += f.y;
        f = __half22float2(bits_h2(u0.y)); acc.z += f.x; acc.w += f.y;
        f = __half22float2(bits_h2(u1.x)); acc.x += f.x; acc.y += f.y;
        f = __half22float2(bits_h2(u1.y)); acc.z += f.x; acc.w += f.y;
        f = __half22float2(bits_h2(u2.x)); acc.x += f.x; acc.y += f.y;
        f = __half22float2(bits_h2(u2.y)); acc.z += f.x; acc.w += f.y;
        f = __half22float2(bits_h2(u3.x)); acc.x += f.x; acc.y += f.y;
        f = __half22float2(bits_h2(u3.y)); acc.z += f.x; acc.w += f.y;
    }
    for (; t < cnt; ++t) {
        const int s = bucket[t];
        const uint2 u = fb[(size_t)s * 32];
        float2 f;
        f = __half22float2(bits_h2(u.x)); acc.x += f.x; acc.y += f.y;
        f = __half22float2(bits_h2(u.y)); acc.z += f.x; acc.w += f.y;
    }
    const float r = 1.0f / fmaxf((float)cnt, 1.0f);
    const __half2 p0 = __floats2half2_rn(acc.x * r, acc.y * r);
    const __half2 p1 = __floats2half2_rn(acc.z * r, acc.w * r);
    *reinterpret_cast<uint2*>(g_hnh + (size_t)node * D + lane * 4) =
        make_uint2(h2_bits(p0), h2_bits(p1));
}

// ===========================================================================
// GEMM: out = [feat16 | hn16] (M x 256) @ Wh + bias, fp16 mma m16n8k16,
// fp32 accumulate. CTA 128x128, 8 warps of 64x32, K chunked at 64.
// Fragments via ldmatrix.m8n8.x4.
// ===========================================================================
#define SROW 36   // u32 per smem row (72 halfs; 36%32=4 -> conflict-free)

__global__ __launch_bounds__(256, 2) void gemm_kernel(
    float* __restrict__ out, int M) {
    __shared__ uint32_t As[128 * SROW];
    __shared__ uint32_t Bs[128 * SROW];

    const int tid  = threadIdx.x;
    const int wid  = tid >> 5;
    const int lane = tid & 31;
    const int blockRow = blockIdx.x * 128;

    const int wm = wid >> 2;               // 0..1 -> rows wm*64
    const int wn = wid & 3;                // 0..3 -> cols wn*32

    const uint32_t As_base = (uint32_t)__cvta_generic_to_shared(As);
    const uint32_t Bs_base = (uint32_t)__cvta_generic_to_shared(Bs);

    const int lm_r  = (lane & 7) + ((lane >> 3) & 1) * 8;  // A row ofs
    const int lm_c  = (lane >> 4) * 4;                     // A k u32 ofs
    const int lmb_r = (lane & 7) + (lane >> 4) * 8;        // B row ofs
    const int lmb_c = ((lane >> 3) & 1) * 4;               // B k u32 ofs

    const int lr[4] = { (0 * 256 + tid) >> 3, (1 * 256 + tid) >> 3,
                        (2 * 256 + tid) >> 3, (3 * 256 + tid) >> 3 };
    const int lc[4] = { (0 * 256 + tid) & 7, (1 * 256 + tid) & 7,
                        (2 * 256 + tid) & 7, (3 * 256 + tid) & 7 };

    uint4 apf[4];

    auto load_a = [&](int it) {
        const int h     = it >> 1;
        const int cbase = (it & 1) * 64;
        const __half* Ag = h ? g_hnh : g_feath;
#pragma unroll
        for (int j = 0; j < 4; ++j) {
            const int grow = blockRow + lr[j];
            apf[j] = (grow < M)
                ? *reinterpret_cast<const uint4*>(
                      Ag + (size_t)grow * D + cbase + lc[j] * 8)
                : make_uint4(0u, 0u, 0u, 0u);
        }
    };
    auto store_a = [&]() {
#pragma unroll
        for (int j = 0; j < 4; ++j)
            *reinterpret_cast<uint4*>(&As[lr[j] * SROW + lc[j] * 4]) = apf[j];
    };
    auto copy_b = [&](int it) {
        const int h     = it >> 1;
        const int cbase = (it & 1) * 64;
        const __half* Wg = g_Wh[h];
#pragma unroll
        for (int j = 0; j < 4; ++j) {
            const uint4 v = *reinterpret_cast<const uint4*>(
                Wg + (size_t)lr[j] * 128 + cbase + lc[j] * 8);
            *reinterpret_cast<uint4*>(&Bs[lr[j] * SROW + lc[j] * 4]) = v;
        }
    };

    float acc[4][4][4];
#pragma unroll
    for (int mt = 0; mt < 4; ++mt)
#pragma unroll
        for (int nt = 0; nt < 4; ++nt)
#pragma unroll
            for (int j = 0; j < 4; ++j) acc[mt][nt][j] = 0.f;

    load_a(0);
    store_a();
    copy_b(0);
    __syncthreads();

#pragma unroll 1
    for (int it = 0; it < 4; ++it) {
        if (it + 1 < 4) load_a(it + 1);    // LDGs in flight during compute

#pragma unroll
        for (int ks = 0; ks < 4; ++ks) {
            const int kb = ks * 8;
            uint32_t a[4][4], bb[2][4];
#pragma unroll
            for (int mt = 0; mt < 4; ++mt) {
                const int rb = wm * 64 + mt * 16;
                const uint32_t sa =
                    As_base + (((rb + lm_r) * SROW + kb + lm_c) << 2);
                ldsm_x4(a[mt][0], a[mt][1], a[mt][2], a[mt][3], sa);
            }
#pragma unroll
            for (int p = 0; p < 2; ++p) {
                const int nb = wn * 32 + p * 16;
                const uint32_t sb =
                    Bs_base + (((nb + lmb_r) * SROW + kb + lmb_c) << 2);
                ldsm_x4(bb[p][0], bb[p][1], bb[p][2], bb[p][3], sb);
            }
#pragma unroll
            for (int mt = 0; mt < 4; ++mt)
#pragma unroll
                for (int nt = 0; nt < 4; ++nt)
                    mma_f16(acc[mt][nt][0], acc[mt][nt][1],
                            acc[mt][nt][2], acc[mt][nt][3],
                            a[mt][0], a[mt][1], a[mt][2], a[mt][3],
                            bb[nt >> 1][(nt & 1) * 2],
                            bb[nt >> 1][(nt & 1) * 2 + 1]);
        }

        if (it + 1 < 4) {
            __syncthreads();
            store_a();
            copy_b(it + 1);
            __syncthreads();
        }
    }

#pragma unroll
    for (int mt = 0; mt < 4; ++mt) {
        const int r0 = blockRow + wm * 64 + mt * 16 + (lane >> 2);
#pragma unroll
        for (int nt = 0; nt < 4; ++nt) {
            const int col = wn * 32 + nt * 8 + (lane & 3) * 2;
            const float b0 = g_bias[col];
            const float b1 = g_bias[col + 1];
            if (r0 < M) {
                float2 o = make_float2(acc[mt][nt][0] + b0, acc[mt][nt][1] + b1);
                *reinterpret_cast<float2*>(out + (size_t)r0 * D + col) = o;
            }
            if (r0 + 8 < M) {
                float2 o = make_float2(acc[mt][nt][2] + b0, acc[mt][nt][3] + b1);
                *reinterpret_cast<float2*>(out + (size_t)(r0 + 8) * D + col) = o;
            }
        }
    }
}

// ---------------------------------------------------------------------------
extern "C" void kernel_launch(void* const* d_in, const int* in_sizes, int n_in,
                              void* d_out, int out_size) {
    const float* feat   = (const float*)d_in[0];
    const int*   src    = (const int*)d_in[1];
    const int*   dst    = (const int*)d_in[2];
    const float* Wself  = (const float*)d_in[3];
    const float* bself  = (const float*)d_in[4];
    const float* Wneigh = (const float*)d_in[5];
    const float* bneigh = (const float*)d_in[6];
    float*       out    = (float*)d_out;

    const int E = in_sizes[1];
    const int M = in_sizes[0] / D;

    prep0_kernel<<<(N_NODES + 255) / 256, 256>>>(Wself, Wneigh, bself, bneigh);
    ec_kernel<<<EC_BLOCKS, 256>>>(feat, src, dst, E);
    agg_kernel<<<(N_NODES * 32 + 255) / 256, 256>>>();
    gemm_kernel<<<(M + 127) / 128, 256>>>(out, M);
}